// round 11
// baseline (speedup 1.0000x reference)
#include <cuda_runtime.h>
#include <cstdint>

// Problem dims
#define BB      128
#define TT      512
#define UU      128
#define NW      80          // N (window/transcription feature dim)
#define HH      512
#define MM      10
#define NKK     322         // packed-pair K rows: 2 (x) + 320 staged (incl. pad)
#define GRID    128
#define BLOCK   512
#define OUT_STRIDE 593      // H + NW + 1
#define NCHUNK  10
#define CHUNKF  64          // floats per chunk per batch row
#define CHUNK_BYTES 32768   // 128 b * 64 f * 4 B
#define GBUF    (NCHUNK * BB * CHUNKF)   // 81920 floats per buffer

// ---------------- device global state (no allocations allowed) ----------------
// g_inp[buf][chunk][b][64]: chunk c holds staged k = 64c..64c+63.
// k 0..511 = h, 512..591 = w, 592..639 = permanent zero pad.
// Within each [b][64] row, 16B group q is stored at slot q ^ (b & 7)  (bank swizzle).
__device__ __align__(128) float g_inp[2 * GBUF];
__device__ float g_kappa[BB * MM];
__device__ unsigned int g_bar;
__device__ unsigned int g_wdone;

// ---------------- helpers ----------------
__device__ __forceinline__ unsigned long long pack2(float x, float y) {
    unsigned long long r;
    asm("mov.b64 %0, {%1, %2};" : "=l"(r) : "f"(x), "f"(y));
    return r;
}
__device__ __forceinline__ void unpack2(unsigned long long v, float &lo, float &hi) {
    asm("mov.b64 {%0, %1}, %2;" : "=f"(lo), "=f"(hi) : "l"(v));
}
// packed fp32x2 FMA (sm_100+): d = a*b + d, lane-wise
__device__ __forceinline__ void ffma2(unsigned long long &d, unsigned long long a, unsigned long long b) {
    asm("fma.rn.f32x2 %0, %1, %2, %0;" : "+l"(d) : "l"(a), "l"(b));
}
__device__ __forceinline__ float sigf(float x) {
    return __fdividef(1.f, 1.f + __expf(-x));
}

__device__ __forceinline__ void grid_barrier(unsigned int target) {
    __threadfence();              // release
    __syncthreads();
    if (threadIdx.x == 0) {
        atomicAdd(&g_bar, 1u);
        volatile unsigned int* vp = &g_bar;
        while (*vp < target) { }
        __threadfence();          // acquire
    }
    __syncthreads();
}

// single-thread bulk-DMA of one 32KB chunk into smem, completion on mbarrier
__device__ __forceinline__ void issue_chunk(uint32_t mbar, uint32_t sdst,
                                            const float* gsrc) {
    asm volatile("mbarrier.arrive.expect_tx.shared::cta.b64 _, [%0], %1;"
                 :: "r"(mbar), "r"(CHUNK_BYTES) : "memory");
    asm volatile("cp.async.bulk.shared::cta.global.mbarrier::complete_tx::bytes "
                 "[%0], [%1], %2, [%3];"
                 :: "r"(sdst), "l"(gsrc), "r"(CHUNK_BYTES), "r"(mbar) : "memory");
}

__device__ __forceinline__ void mbar_wait(uint32_t mbar, unsigned int parity) {
    asm volatile(
        "{\n\t"
        ".reg .pred P;\n\t"
        "LAB_%=:\n\t"
        "mbarrier.try_wait.parity.acquire.cta.shared::cta.b64 P, [%0], %1, 0x989680;\n\t"
        "@!P bra LAB_%=;\n\t"
        "}"
        :: "r"(mbar), "r"(parity) : "memory");
}

// ---------------- init kernel (reset state every replay) ----------------
__global__ void rnn_init_kernel() {
    int tid = blockIdx.x * blockDim.x + threadIdx.x;
    int nthr = gridDim.x * blockDim.x;
    for (int i = tid; i < 2 * GBUF; i += nthr) g_inp[i] = 0.f;
    for (int i = tid; i < BB * MM; i += nthr) g_kappa[i] = 0.f;
    if (tid == 0) { g_bar = 0u; g_wdone = 0u; }
}

// ---------------- shared memory layout (dynamic) ----------------
#define OFF_MBAR 0                       // 2 mbarriers, 16 B
#define OFF_WP   16                      // 322*32 floats = 41216 B
#define OFF_WD   41232                   // 512*30 floats = 61440 B
#define OFF_TR   102672                  // 128*80 floats = 40960 B
#define OFF_IN   143744                  // 2*8192 floats = 65536 B (128B aligned)
#define OFF_H    209280                  // 512 floats    = 2048 B
#define OFF_YP   211328                  // 480 floats    = 1920 B
#define OFF_WF   213248                  // 136 floats    = 544 B
#define OFF_Y    213792                  // 32 floats     = 128 B
#define OFF_BD   213920                  // 32 floats     = 128 B
#define OFF_A    214048                  // 16 floats     = 64 B
#define OFF_BE   214112                  // 16 floats     = 64 B
#define OFF_KA   214176                  // 16 floats     = 64 B
#define OFF_BIAS 214240                  // 16 floats     = 64 B
#define SMEM_BYTES 214304

extern __shared__ char smem_raw[];

__global__ void __launch_bounds__(BLOCK, 1)
rnn_persistent_kernel(const float* __restrict__ strokes,
                      const float* __restrict__ trans,
                      const float* __restrict__ Wx,
                      const float* __restrict__ Wh,
                      const float* __restrict__ bvec,
                      const float* __restrict__ Wd,
                      const float* __restrict__ bd,
                      float* __restrict__ out) {
    float* sWp   = (float*)(smem_raw + OFF_WP);    // [NKK][4 col][4 gate][2 lane]
    float* sWd   = (float*)(smem_raw + OFF_WD);    // [512][30]
    float* sTr   = (float*)(smem_raw + OFF_TR);    // [128][80]
    float* sIn   = (float*)(smem_raw + OFF_IN);    // [2][128][64] staging
    float* s_h   = (float*)(smem_raw + OFF_H);     // [512]
    float* s_yp  = (float*)(smem_raw + OFF_YP);    // [480]
    float* s_wf  = (float*)(smem_raw + OFF_WF);    // [129]
    float* s_y   = (float*)(smem_raw + OFF_Y);     // [30]
    float* s_bd  = (float*)(smem_raw + OFF_BD);    // [30]
    float* s_a   = (float*)(smem_raw + OFF_A);     // [10]
    float* s_be  = (float*)(smem_raw + OFF_BE);    // [10]
    float* s_ka  = (float*)(smem_raw + OFF_KA);    // [10]
    float* sBias = (float*)(smem_raw + OFF_BIAS);  // [4 col][4 gate]

    const uint32_t smem_base = (uint32_t)__cvta_generic_to_shared(smem_raw);
    const uint32_t mbar0 = smem_base + OFF_MBAR;
    const uint32_t mbar1 = smem_base + OFF_MBAR + 8;
    const uint32_t sIn32 = smem_base + OFF_IN;

    const int tid = threadIdx.x;
    const int b   = tid >> 2;            // batch row (GEMM phase): 8 per warp
    const int col = tid & 3;             // owned column within CTA's 4
    const int qb  = b & 7;               // 16B-group swizzle key for vv loads
    const int bb  = blockIdx.x;          // CTA == batch row in attention phase
    const int j0  = blockIdx.x * 4;      // owned h-columns [j0, j0+4)

    // ---- mbarrier init ----
    if (tid == 0) {
        asm volatile("mbarrier.init.shared.b64 [%0], 1;" :: "r"(mbar0) : "memory");
        asm volatile("mbarrier.init.shared.b64 [%0], 1;" :: "r"(mbar1) : "memory");
        asm volatile("fence.proxy.async.shared::cta;" ::: "memory");
    }

    // ---- one-time weight staging ----
    // sWp[kk][col][gate][lane]: lane 0 = even-k weight, lane 1 = odd-k weight.
    // kk 0: k=(x0,x1); kk 1: k=(x2, pad); kk>=2: staged rows s=2(kk-2)+lane
    //   (s<512 -> Wh row s; s<592 -> Wx row 3+(s-512) (w inputs); else 0 pad).
    for (int i = tid; i < NKK * 32; i += BLOCK) {
        int kk = i >> 5, rem = i & 31;
        int c_ = rem >> 3, e = rem & 7, gate = e >> 1, lane = e & 1;
        int colg = (gate << 9) + j0 + c_;
        float val;
        if (kk >= 2) {
            int s = 2 * (kk - 2) + lane;
            if (s < HH)            val = Wh[s * 2048 + colg];
            else if (s < HH + NW)  val = Wx[(3 + s - HH) * 2048 + colg];
            else                   val = 0.f;
        } else {
            int k = kk * 2 + lane;
            val = (k < 3) ? Wx[k * 2048 + colg] : 0.f;
        }
        sWp[i] = val;
    }
    if (tid < 16) {
        int c_ = tid >> 2, gate = tid & 3;
        sBias[tid] = bvec[(gate << 9) + j0 + c_];
    }
    for (int i = tid; i < HH * 30; i += BLOCK) sWd[i] = Wd[i];
    if (tid < 30) s_bd[tid] = bd[tid];
    for (int i = tid; i < UU * NW; i += BLOCK) sTr[i] = trans[bb * UU * NW + i];
    __syncthreads();

    float creg = 0.f;                    // c-state for this thread's (b, col)
    unsigned int tgt = 0;

    // prologue: prime chunks 0,1 of t=0 (buffer 0 is all zeros — h0 = w0 = 0)
    if (tid == 0) {
        issue_chunk(mbar0, sIn32,               g_inp);
        issue_chunk(mbar1, sIn32 + CHUNK_BYTES, g_inp + BB * CHUNKF);
    }

    for (int t = 0; t < TT; ++t) {
        const float* __restrict__ gin = g_inp + (t & 1) * GBUF;
        float* __restrict__ gnext = g_inp + ((t + 1) & 1) * GBUF;

        // =========== Phase A: z for 4 gates of (b, j0+col) ===========
        unsigned long long a_i = pack2(sBias[col * 4 + 0], 0.f);
        unsigned long long a_f = pack2(sBias[col * 4 + 1], 0.f);
        unsigned long long a_g = pack2(sBias[col * 4 + 2], 0.f);
        unsigned long long a_o = pack2(sBias[col * 4 + 3], 0.f);

        // x contribution (kk rows 0,1) — overlaps with in-flight DMA
        {
            const float* xp = strokes + ((size_t)b * TT + t) * 3;
            unsigned long long vx0 = pack2(xp[0], xp[1]);
            unsigned long long vx1 = pack2(xp[2], 0.f);
            const ulonglong2* w0 = (const ulonglong2*)(sWp + col * 8);
            const ulonglong2* w1 = (const ulonglong2*)(sWp + 32 + col * 8);
            ulonglong2 wA0 = w0[0], wA1 = w0[1], wB0 = w1[0], wB1 = w1[1];
            ffma2(a_i, vx0, wA0.x); ffma2(a_f, vx0, wA0.y);
            ffma2(a_g, vx0, wA1.x); ffma2(a_o, vx0, wA1.y);
            ffma2(a_i, vx1, wB0.x); ffma2(a_f, vx1, wB0.y);
            ffma2(a_g, vx1, wB1.x); ffma2(a_o, vx1, wB1.y);
        }

        const unsigned int wtarget = (unsigned int)t * GRID;

        for (int c = 0; c < NCHUNK; ++c) {
            const int s = c & 1;
            // use index of buffer s this step = c>>1; parity = (t + c/2) & 1
            mbar_wait(s ? mbar1 : mbar0, (unsigned int)((t + (c >> 1)) & 1));

            const float* sb = sIn + s * (BB * CHUNKF) + b * CHUNKF;
            // kk row for staged row 64c is 32c+2
            const ulonglong2* wbase =
                (const ulonglong2*)(sWp + (32 * c + 2) * 32 + col * 8);
#pragma unroll 4
            for (int q = 0; q < 16; ++q) {
                // broadcast-friendly 16B load: slot q^qb holds k-group q of row b
                ulonglong2 vv = *(const ulonglong2*)(sb + ((q ^ qb) << 2));
                const ulonglong2* w = wbase + q * 16;           // 2 kk rows per q
                ulonglong2 wA0 = w[0], wA1 = w[1];              // kk   : (i,f),(g,o)
                ulonglong2 wB0 = w[8], wB1 = w[9];              // kk+1
                ffma2(a_i, vv.x, wA0.x); ffma2(a_f, vv.x, wA0.y);
                ffma2(a_g, vv.x, wA1.x); ffma2(a_o, vv.x, wA1.y);
                ffma2(a_i, vv.y, wB0.x); ffma2(a_f, vv.y, wB0.y);
                ffma2(a_g, vv.y, wB1.x); ffma2(a_o, vv.y, wB1.y);
            }
            __syncthreads();           // all lanes done with buffer s
            if (c + 2 < NCHUNK && tid == 0) {
                if (c == 6) {
                    // chunks 8,9 carry w_{t-1}: wait for all CTAs' phase C(t-1)
                    volatile unsigned int* vp = &g_wdone;
                    while (*vp < wtarget) { }
                    __threadfence();
                }
                issue_chunk(s ? mbar1 : mbar0,
                            sIn32 + s * CHUNK_BYTES,
                            gin + (c + 2) * (BB * CHUNKF));
            }
        }

        // =========== Phase B: LSTM pointwise update (1 column / thread) ===========
        {
            float lo, hi;
            unpack2(a_i, lo, hi); float zi = lo + hi;
            unpack2(a_f, lo, hi); float zf = lo + hi;
            unpack2(a_g, lo, hi); float zg = lo + hi;
            unpack2(a_o, lo, hi); float zo = lo + hi;

            float cn = sigf(zf) * creg + sigf(zi) * tanhf(zg);
            float hn = sigf(zo) * tanhf(cn); creg = cn;

            int k = j0 + col;            // staged row index of this h column
            out[((size_t)b * TT + t) * OUT_STRIDE + k] = hn;
            // swizzled global store matching consumer layout:
            // chunk = k>>6, group q = (k>>2)&15, slot = q ^ (b&7), elem = k&3
            int q = (k >> 2) & 15;
            gnext[(k >> 6) * (BB * CHUNKF) + b * CHUNKF +
                  (((q ^ qb) << 2) | (k & 3))] = hn;
        }

        tgt += GRID;
        grid_barrier(tgt);   // all h_new visible (in out[] and next g_inp buf)

        // prime chunks 0,1 of step t+1 NOW, so the DMA runs under phase C
        if (t + 1 < TT && tid == 0) {
            issue_chunk(mbar0, sIn32,               gnext);
            issue_chunk(mbar1, sIn32 + CHUNK_BYTES, gnext + BB * CHUNKF);
        }

        // =========== Phase C: attention head for batch row bb ===========
        {
            float* orow = out + ((size_t)bb * TT + t) * OUT_STRIDE;

            s_h[tid] = orow[tid];       // BLOCK==HH: coalesced own-row h read
            __syncthreads();

            // y = h @ Wd  (30 outputs, 16-way K split over 480 threads)
            if (tid < 480) {
                int n = tid >> 4, q = tid & 15;
                int k0 = q * 32;
                float p0 = 0.f, p1 = 0.f, p2 = 0.f, p3 = 0.f;
#pragma unroll 4
                for (int k = k0; k < k0 + 32; k += 4) {
                    p0 = fmaf(s_h[k],     sWd[(k)     * 30 + n], p0);
                    p1 = fmaf(s_h[k + 1], sWd[(k + 1) * 30 + n], p1);
                    p2 = fmaf(s_h[k + 2], sWd[(k + 2) * 30 + n], p2);
                    p3 = fmaf(s_h[k + 3], sWd[(k + 3) * 30 + n], p3);
                }
                s_yp[tid] = (p0 + p1) + (p2 + p3);
            }
            __syncthreads();
            if (tid < 30) {
                float s = 0.f;
#pragma unroll
                for (int q = 0; q < 16; ++q) s += s_yp[tid * 16 + q];
                s_y[tid] = __expf(s + s_bd[tid]);
            }
            __syncthreads();
            if (tid < MM) {
                float ka = g_kappa[bb * MM + tid] + s_y[20 + tid];
                g_kappa[bb * MM + tid] = ka;
                s_ka[tid] = ka;
                s_a[tid]  = s_y[tid];
                s_be[tid] = s_y[10 + tid];
            }
            __syncthreads();

            // phi / wfull over u = 0..128
            if (tid <= UU) {
                float fu = (float)tid;
                float acc = 0.f;
#pragma unroll
                for (int m = 0; m < MM; ++m) {
                    float d = s_ka[m] - fu;
                    acc = fmaf(s_a[m], __expf(-s_be[m] * d * d), acc);
                }
                s_wf[tid] = acc;
            }
            __syncthreads();

            // argmax (first-max tie rule), warp 0
            if (tid < 32) {
                float bv = -3.4e38f; int bi = 0;
                for (int u = tid; u <= UU; u += 32) {
                    float v = s_wf[u];
                    if (v > bv) { bv = v; bi = u; }
                }
                for (int off = 16; off; off >>= 1) {
                    float ov = __shfl_xor_sync(0xffffffffu, bv, off);
                    int   oi = __shfl_xor_sync(0xffffffffu, bi, off);
                    if (ov > bv || (ov == bv && oi < bi)) { bv = ov; bi = oi; }
                }
                if (tid == 0) orow[HH + NW] = (float)bi;
            }

            // w = wfull[:U] @ transcriptions[bb]
            if (tid < NW) {
                float a0 = 0.f, a1 = 0.f, a2 = 0.f, a3 = 0.f;
#pragma unroll 4
                for (int u = 0; u < UU; u += 4) {
                    a0 = fmaf(s_wf[u],     sTr[(u)     * NW + tid], a0);
                    a1 = fmaf(s_wf[u + 1], sTr[(u + 1) * NW + tid], a1);
                    a2 = fmaf(s_wf[u + 2], sTr[(u + 2) * NW + tid], a2);
                    a3 = fmaf(s_wf[u + 3], sTr[(u + 3) * NW + tid], a3);
                }
                float wv = (a0 + a1) + (a2 + a3);
                // swizzled global store for staged row k = 512+tid (owner row = bb)
                int k = HH + tid;
                int q = (k >> 2) & 15;
                gnext[(k >> 6) * (BB * CHUNKF) + bb * CHUNKF +
                      (((q ^ (bb & 7)) << 2) | (k & 3))] = wv;
                orow[HH + tid] = wv;
            }

            __syncthreads();
            if (tid == 0) {            // signal w_t ready (consumed at chunk 8 of t+1)
                __threadfence();
                atomicAdd(&g_wdone, 1u);
            }
        }
    }
}

// ---------------- launch ----------------
extern "C" void kernel_launch(void* const* d_in, const int* in_sizes, int n_in,
                              void* d_out, int out_size) {
    const float* strokes = (const float*)d_in[0];
    const float* trans   = (const float*)d_in[1];
    // d_in[2] = enumerated (0..128) -- recomputed on the fly
    const float* Wx      = (const float*)d_in[3];
    const float* Wh      = (const float*)d_in[4];
    const float* bvec    = (const float*)d_in[5];
    const float* Wd      = (const float*)d_in[6];
    const float* bd      = (const float*)d_in[7];
    float* out = (float*)d_out;

    cudaFuncSetAttribute(rnn_persistent_kernel,
                         cudaFuncAttributeMaxDynamicSharedMemorySize, SMEM_BYTES);

    rnn_init_kernel<<<32, 256>>>();
    rnn_persistent_kernel<<<GRID, BLOCK, SMEM_BYTES>>>(strokes, trans, Wx, Wh,
                                                       bvec, Wd, bd, out);
}

// round 13
// speedup vs baseline: 1.4597x; 1.4597x over previous
#include <cuda_runtime.h>
#include <cstdint>

// Problem dims
#define BB      128
#define TT      512
#define UU      128
#define NW      80
#define HH      512
#define MM      10
#define GRID    128
#define BLOCK   512
#define OUT_STRIDE 593
#define NCH     20                      // 20 chunks x 32 k
#define NKKT    320                     // total packed k-pair rows (640 k)
#define CHUNK_BYTES 16384               // 16 kk x 128 b x 8 B
#define GBUF_FLOATS (NCH * CHUNK_BYTES / 4)   // 81920 floats per buffer

// ---------------- device global state ----------------
// g_inp[buf][chunk][kk_local][b][2]: k 0..511 = h, 512..591 = w, 592..594 = x, rest 0.
__device__ __align__(128) float g_inp[2 * GBUF_FLOATS];
__device__ float g_kappa[BB * MM];
__device__ unsigned int g_bar;
__device__ unsigned int g_wdone;

// ---------------- helpers ----------------
__device__ __forceinline__ void unpack2(unsigned long long v, float &lo, float &hi) {
    asm("mov.b64 {%0, %1}, %2;" : "=f"(lo), "=f"(hi) : "l"(v));
}
__device__ __forceinline__ void ffma2(unsigned long long &d, unsigned long long a,
                                      unsigned long long b) {
    asm("fma.rn.f32x2 %0, %1, %2, %0;" : "+l"(d) : "l"(a), "l"(b));
}
__device__ __forceinline__ float sigf(float x) {
    return __fdividef(1.f, 1.f + __expf(-x));
}
// byte offset of element (b, k) inside one A buffer
__device__ __forceinline__ int a_idx(int b, int k) {
    return (k >> 5) * CHUNK_BYTES + ((k >> 1) & 15) * 1024 + b * 8 + (k & 1) * 4;
}
__device__ __forceinline__ void issue_chunk(uint32_t mbar, uint32_t sdst,
                                            const void* gsrc) {
    asm volatile("mbarrier.arrive.expect_tx.shared::cta.b64 _, [%0], %1;"
                 :: "r"(mbar), "r"((uint32_t)CHUNK_BYTES) : "memory");
    asm volatile("cp.async.bulk.shared::cta.global.mbarrier::complete_tx::bytes "
                 "[%0], [%1], %2, [%3];"
                 :: "r"(sdst), "l"(gsrc), "r"((uint32_t)CHUNK_BYTES), "r"(mbar)
                 : "memory");
}
__device__ __forceinline__ void mbar_wait(uint32_t mbar, int parity) {
    asm volatile(
        "{\n\t.reg .pred P;\n\tLAB_%=:\n\t"
        "mbarrier.try_wait.parity.acquire.cta.shared::cta.b64 P, [%0], %1, 0x989680;\n\t"
        "@!P bra LAB_%=;\n\t}"
        :: "r"(mbar), "r"((unsigned)parity) : "memory");
}
__device__ __forceinline__ void grid_barrier(unsigned int target) {
    __threadfence();
    __syncthreads();
    if (threadIdx.x == 0) {
        atomicAdd(&g_bar, 1u);
        volatile unsigned int* vp = &g_bar;
        while (*vp < target) { }
        __threadfence();
    }
    __syncthreads();
}

// ---------------- init kernel ----------------
__global__ void rnn_init_kernel() {
    int tid = blockIdx.x * blockDim.x + threadIdx.x;
    int nthr = gridDim.x * blockDim.x;
    for (int i = tid; i < 2 * GBUF_FLOATS; i += nthr) g_inp[i] = 0.f;
    for (int i = tid; i < BB * MM; i += nthr) g_kappa[i] = 0.f;
    if (tid == 0) { g_bar = 0u; g_wdone = 0u; }
}

// ---------------- smem layout ----------------
#define OFF_MBAR  0        // 4 mbarriers (8B each)
#define OFF_BIAS  64       // 16 floats
#define OFF_WP    1024     // 320*32 floats = 40960 B
#define OFF_WD    41984    // 512*30 floats = 61440 B
#define OFF_AIN   103424   // 4 x 16384 = 65536 B (1024-aligned)
#define OFF_Z     168960   // 128*16 ulonglong = 16384 B
#define OFF_H     185344   // 512 floats
#define OFF_YP    187392   // 480 floats
#define OFF_WF    189312   // 136 floats
#define OFF_Y     189856   // 32 floats
#define OFF_BD    189984   // 32 floats
#define OFF_A2    190112   // 16 floats
#define OFF_BE2   190176   // 16 floats
#define OFF_KA2   190240   // 16 floats
#define SMEM_BYTES 190336

extern __shared__ char smem_raw[];

__global__ void __launch_bounds__(BLOCK, 1)
rnn_persistent_kernel(const float* __restrict__ strokes,
                      const float* __restrict__ trans,
                      const float* __restrict__ Wx,
                      const float* __restrict__ Wh,
                      const float* __restrict__ bvec,
                      const float* __restrict__ Wd,
                      const float* __restrict__ bd,
                      float* __restrict__ out) {
    float* sWp   = (float*)(smem_raw + OFF_WP);   // [320 kk][4 cg][4 gate][2 lane]
    float* sWd   = (float*)(smem_raw + OFF_WD);   // [512][30]
    unsigned long long* sZ = (unsigned long long*)(smem_raw + OFF_Z); // [128 b][16]
    float* s_h   = (float*)(smem_raw + OFF_H);
    float* s_yp  = (float*)(smem_raw + OFF_YP);
    float* s_wf  = (float*)(smem_raw + OFF_WF);
    float* s_y   = (float*)(smem_raw + OFF_Y);
    float* s_bd  = (float*)(smem_raw + OFF_BD);
    float* s_a   = (float*)(smem_raw + OFF_A2);
    float* s_be  = (float*)(smem_raw + OFF_BE2);
    float* s_ka  = (float*)(smem_raw + OFF_KA2);
    float* sBias = (float*)(smem_raw + OFF_BIAS); // [4 cg][4 gate]

    const uint32_t smem_base = (uint32_t)__cvta_generic_to_shared(smem_raw);
    const uint32_t sAin32 = smem_base + OFF_AIN;

    const int tid  = threadIdx.x;
    const int wid  = tid >> 5;
    const int lid  = tid & 31;
    const int half = wid >> 3;           // k-half: 0 -> k<320, 1 -> k>=320
    const int cg   = lid >> 3;           // owned h-col within CTA (0..3)
    const int bgrp = lid & 7;
    const int bloc = (wid & 7) * 16 + bgrp * 2;   // first of 2 owned batch rows
    const int bb   = blockIdx.x;         // CTA == batch row in attention phase
    const int j0   = blockIdx.x * 4;     // owned h-columns [j0, j0+4)

    // stream constants for this half
    const int base = half * 10;          // first chunk index of this half
    const uint32_t mbA = smem_base + OFF_MBAR + (half * 2) * 8;
    const uint32_t mbB = mbA + 8;
    const uint32_t bufA = sAin32 + (half * 2) * CHUNK_BYTES;
    const uint32_t bufB = bufA + CHUNK_BYTES;

    // ---- mbarrier init ----
    if (tid == 0) {
#pragma unroll
        for (int m = 0; m < 4; ++m)
            asm volatile("mbarrier.init.shared.b64 [%0], 1;"
                         :: "r"(smem_base + OFF_MBAR + m * 8) : "memory");
        asm volatile("fence.proxy.async.shared::cta;" ::: "memory");
    }

    // ---- one-time weight staging ----
    // sWp[kk][cg][gate][lane]: lane 0 = even k (2kk), lane 1 = odd k (2kk+1)
    for (int i = tid; i < NKKT * 32; i += BLOCK) {
        int kk = i >> 5, rem = i & 31;
        int c_ = rem >> 3, e = rem & 7, gate = e >> 1, lane = e & 1;
        int col = (gate << 9) + j0 + c_;
        int k = 2 * kk + lane;
        float val;
        if (k < HH)                 val = Wh[k * 2048 + col];
        else if (k < HH + NW)       val = Wx[(3 + k - HH) * 2048 + col];
        else if (k < HH + NW + 3)   val = Wx[(k - (HH + NW)) * 2048 + col];
        else                        val = 0.f;
        sWp[i] = val;
    }
    if (tid < 16) {
        int c_ = tid >> 2, gate = tid & 3;
        sBias[tid] = bvec[(gate << 9) + j0 + c_];
    }
    for (int i = tid; i < HH * 30; i += BLOCK) sWd[i] = Wd[i];
    if (tid < 30) s_bd[tid] = bd[tid];
    __syncthreads();

    // prologue: write x_0 for own batch row, make globally visible
    if (tid < 3) {
        *(float*)((char*)g_inp + a_idx(bb, HH + NW + tid)) =
            strokes[(size_t)bb * TT * 3 + tid];
    }
    unsigned int tgt = GRID;
    grid_barrier(tgt);

    // prime both streams for t=0
    if (tid == 0) {
        issue_chunk(mbA, bufA, (const char*)g_inp + (base + 0) * CHUNK_BYTES);
        issue_chunk(mbB, bufB, (const char*)g_inp + (base + 1) * CHUNK_BYTES);
    }
    if (tid == 256) {
        issue_chunk(mbA, bufA, (const char*)g_inp + (base + 0) * CHUNK_BYTES);
        issue_chunk(mbB, bufB, (const char*)g_inp + (base + 1) * CHUNK_BYTES);
    }

    int pA = 0, pB = 0;                  // per-buffer phase parity (this half)
    float c0 = 0.f, c1 = 0.f;            // LSTM c-state (half 0 lanes only)

    for (int t = 0; t < TT; ++t) {
        const char* gin   = (const char*)(g_inp + (t & 1) * GBUF_FLOATS);
        char*       gnext = (char*)(g_inp + ((t + 1) & 1) * GBUF_FLOATS);

        // ===== Phase A: 8 FFMA2 per kk per lane (2 b x 4 gates), own k-half =====
        unsigned long long a00 = 0, a01 = 0, a02 = 0, a03 = 0;  // batch b, gates ifgo
        unsigned long long a10 = 0, a11 = 0, a12 = 0, a13 = 0;  // batch b+1

        const unsigned int wtarget = (unsigned int)t * GRID;

        for (int ci = 0; ci < 10; ++ci) {
            const int sbuf = ci & 1;
            mbar_wait(sbuf ? mbB : mbA, sbuf ? pB : pA);
            if (sbuf) pB ^= 1; else pA ^= 1;

            const char* sb = smem_raw + OFF_AIN +
                             (half * 2 + sbuf) * CHUNK_BYTES + bloc * 8;
            const float* wr0 = sWp + ((base + ci) << 4) * 32 + cg * 8;
#pragma unroll 4
            for (int j = 0; j < 16; ++j) {
                ulonglong2 vv = *(const ulonglong2*)(sb + j * 1024);
                const ulonglong2* wr = (const ulonglong2*)(wr0 + j * 32);
                ulonglong2 wlo = wr[0], whi = wr[1];   // gates (i,f), (g,o)
                ffma2(a00, vv.x, wlo.x); ffma2(a01, vv.x, wlo.y);
                ffma2(a02, vv.x, whi.x); ffma2(a03, vv.x, whi.y);
                ffma2(a10, vv.y, wlo.x); ffma2(a11, vv.y, wlo.y);
                ffma2(a12, vv.y, whi.x); ffma2(a13, vv.y, whi.y);
            }
            asm volatile("bar.sync %0, 256;" :: "r"(1 + half) : "memory");

            if (ci < 8 && (tid == 0 || tid == 256)) {
                int nc = base + ci + 2;
                if (half == 1 && ci == 4) {
                    // chunks >=16 carry w_{t-1}, x_t from all CTAs' phase C(t-1)
                    volatile unsigned int* vp = &g_wdone;
                    while (*vp < wtarget) { }
                    __threadfence();
                }
                issue_chunk(sbuf ? mbB : mbA,
                            (sbuf ? bufB : bufA),
                            gin + nc * CHUNK_BYTES);
            }
        }

        // ===== z exchange: half1 stores partials, half0 reduces + LSTM =====
        if (half == 1) {
            unsigned long long* zp = sZ + bloc * 16 + cg * 4;
            zp[0] = a00; zp[1] = a01; zp[2] = a02; zp[3] = a03;
            zp += 16;
            zp[0] = a10; zp[1] = a11; zp[2] = a12; zp[3] = a13;
        }
        __syncthreads();

        if (half == 0) {
            const unsigned long long* zp = sZ + bloc * 16 + cg * 4;
            float lo, hi, l2, h2;
#define REDZ(acc, part, bias, dst) { unpack2(acc, lo, hi); unpack2(part, l2, h2); \
            dst = ((lo + l2) + (hi + h2)) + bias; }
            float zi, zf, zg, zo;
            float bi_ = sBias[cg * 4 + 0], bf_ = sBias[cg * 4 + 1];
            float bg_ = sBias[cg * 4 + 2], bo_ = sBias[cg * 4 + 3];

            REDZ(a00, zp[0], bi_, zi); REDZ(a01, zp[1], bf_, zf);
            REDZ(a02, zp[2], bg_, zg); REDZ(a03, zp[3], bo_, zo);
            float cn = sigf(zf) * c0 + sigf(zi) * tanhf(zg);
            float hn = sigf(zo) * tanhf(cn); c0 = cn;
            out[((size_t)bloc * TT + t) * OUT_STRIDE + j0 + cg] = hn;
            *(float*)(gnext + a_idx(bloc, j0 + cg)) = hn;

            zp += 16;
            REDZ(a10, zp[0], bi_, zi); REDZ(a11, zp[1], bf_, zf);
            REDZ(a12, zp[2], bg_, zg); REDZ(a13, zp[3], bo_, zo);
            cn = sigf(zf) * c1 + sigf(zi) * tanhf(zg);
            hn = sigf(zo) * tanhf(cn); c1 = cn;
            out[((size_t)(bloc + 1) * TT + t) * OUT_STRIDE + j0 + cg] = hn;
            *(float*)(gnext + a_idx(bloc + 1, j0 + cg)) = hn;
#undef REDZ
        }

        tgt += GRID;
        grid_barrier(tgt);               // all h_new visible everywhere

        // prime both streams for step t+1 (h chunks; DMA overlaps phase C)
        if (t + 1 < TT && (tid == 0 || tid == 256)) {
            issue_chunk(mbA, bufA, gnext + (base + 0) * CHUNK_BYTES);
            issue_chunk(mbB, bufB, gnext + (base + 1) * CHUNK_BYTES);
        }

        // ===== Phase C: attention head for batch row bb =====
        {
            float* orow = out + ((size_t)bb * TT + t) * OUT_STRIDE;

            s_h[tid] = orow[tid];        // BLOCK == HH
            __syncthreads();

            // y = h @ Wd  (30 outputs, 16-way K split over 480 threads)
            if (tid < 480) {
                int n = tid >> 4, q = tid & 15;
                int k0 = q * 32;
                float p0 = 0.f, p1 = 0.f, p2 = 0.f, p3 = 0.f;
#pragma unroll 4
                for (int k = k0; k < k0 + 32; k += 4) {
                    p0 = fmaf(s_h[k],     sWd[(k)     * 30 + n], p0);
                    p1 = fmaf(s_h[k + 1], sWd[(k + 1) * 30 + n], p1);
                    p2 = fmaf(s_h[k + 2], sWd[(k + 2) * 30 + n], p2);
                    p3 = fmaf(s_h[k + 3], sWd[(k + 3) * 30 + n], p3);
                }
                s_yp[tid] = (p0 + p1) + (p2 + p3);
            }
            __syncthreads();
            if (tid < 30) {
                float s = 0.f;
#pragma unroll
                for (int q = 0; q < 16; ++q) s += s_yp[tid * 16 + q];
                s_y[tid] = __expf(s + s_bd[tid]);
            }
            __syncthreads();
            if (tid < MM) {
                float ka = g_kappa[bb * MM + tid] + s_y[20 + tid];
                g_kappa[bb * MM + tid] = ka;
                s_ka[tid] = ka;
                s_a[tid]  = s_y[tid];
                s_be[tid] = s_y[10 + tid];
            }
            __syncthreads();

            if (tid <= UU) {
                float fu = (float)tid, acc = 0.f;
#pragma unroll
                for (int m = 0; m < MM; ++m) {
                    float d = s_ka[m] - fu;
                    acc = fmaf(s_a[m], __expf(-s_be[m] * d * d), acc);
                }
                s_wf[tid] = acc;
            }
            __syncthreads();

            if (tid < 32) {              // argmax, first-max tie rule
                float bv = -3.4e38f; int bi = 0;
                for (int u = tid; u <= UU; u += 32) {
                    float v = s_wf[u];
                    if (v > bv) { bv = v; bi = u; }
                }
                for (int off = 16; off; off >>= 1) {
                    float ov = __shfl_xor_sync(0xffffffffu, bv, off);
                    int   oi = __shfl_xor_sync(0xffffffffu, bi, off);
                    if (ov > bv || (ov == bv && oi < bi)) { bv = ov; bi = oi; }
                }
                if (tid == 0) orow[HH + NW] = (float)bi;
            }

            // w = wfull[:U] @ transcriptions[bb]   (trans from L2)
            if (tid < NW) {
                const float* tr = trans + (size_t)bb * UU * NW + tid;
                float a0 = 0.f, a1 = 0.f, a2 = 0.f, a3 = 0.f;
#pragma unroll 4
                for (int u = 0; u < UU; u += 4) {
                    a0 = fmaf(s_wf[u],     tr[(u)     * NW], a0);
                    a1 = fmaf(s_wf[u + 1], tr[(u + 1) * NW], a1);
                    a2 = fmaf(s_wf[u + 2], tr[(u + 2) * NW], a2);
                    a3 = fmaf(s_wf[u + 3], tr[(u + 3) * NW], a3);
                }
                float wv = (a0 + a1) + (a2 + a3);
                *(float*)(gnext + a_idx(bb, HH + tid)) = wv;
                orow[HH + tid] = wv;
            }

            // x_{t+1} for own row
            if (t + 1 < TT && tid < 3) {
                *(float*)(gnext + a_idx(bb, HH + NW + tid)) =
                    strokes[(size_t)bb * TT * 3 + (t + 1) * 3 + tid];
            }

            __syncthreads();
            if (tid == 0) {              // signal w_t / x_{t+1} ready
                __threadfence();
                atomicAdd(&g_wdone, 1u);
            }
        }
    }
}

// ---------------- launch ----------------
extern "C" void kernel_launch(void* const* d_in, const int* in_sizes, int n_in,
                              void* d_out, int out_size) {
    const float* strokes = (const float*)d_in[0];
    const float* trans   = (const float*)d_in[1];
    // d_in[2] = enumerated -- recomputed on the fly
    const float* Wx      = (const float*)d_in[3];
    const float* Wh      = (const float*)d_in[4];
    const float* bvec    = (const float*)d_in[5];
    const float* Wd      = (const float*)d_in[6];
    const float* bd      = (const float*)d_in[7];
    float* out = (float*)d_out;

    cudaFuncSetAttribute(rnn_persistent_kernel,
                         cudaFuncAttributeMaxDynamicSharedMemorySize, SMEM_BYTES);

    rnn_init_kernel<<<32, 256>>>();
    rnn_persistent_kernel<<<GRID, BLOCK, SMEM_BYTES>>>(strokes, trans, Wx, Wh,
                                                       bvec, Wd, bd, out);
}